// round 16
// baseline (speedup 1.0000x reference)
#include <cuda_runtime.h>
#include <cuda_fp16.h>
#include <math.h>

#define B 64
#define S 512
#define H 512
#define IN 84
#define NC 100
#define XW 266

#define NGRP 4
#define GCTA 32
#define BPG 16
#define UPC 16
#define NCTA 128
#define NTH 256

// padded strides (halves): row stride ≡ odd*16 B mod 128 -> conflict-free ldmatrix
#define WST 648
#define XHST 520
#define XFST 136

// ---- static device scratch ----
__device__ unsigned short g_hx[2 * NGRP * 16 * XHST];            // [par][grp][16b][520] fp16
__device__ unsigned short g_fx[(size_t)S * NGRP * 16 * XFST];    // [s][grp][16b][136] fp16
__device__ float g_lstm[(size_t)S * H * B];                      // [S][H][B]
__device__ float g_sc[S * B];
__device__ float g_ctx[H * B];
__device__ unsigned g_ctrs[64];

// ---- SMEM layout (bytes) ----
#define OFF_WHI   0                     // 64 x 648 fp16 = 82944
#define OFF_XH    82944                 // 16 x 520 fp16 = 16640 (chunk0: rows 0-7, chunk1: rows 8-15)
#define OFF_XF    99584                 // 2 bufs x 16 x 136 fp16 = 8704
#define OFF_GSH   108288                // 2 planes x 64 x 17 f32 = 8704
#define OFF_HOUT  116992                // 16 x 17 f32
#define OFF_MB    118080                // 4 mbars: h0, h1, f0, f1
#define SMEM_BYTES 118112
#define XFBUF 4352                      // bytes per feats buffer
#define XHCHUNK 8320                    // h half-plane bytes (8 batches x 520 x 2)
#define GSHPL 1088                      // floats per gsh plane (64*17)

// ---- helpers ----
__device__ __forceinline__ unsigned smem_u32(const void* p) {
    return (unsigned)__cvta_generic_to_shared(p);
}
__device__ __forceinline__ void mbar_init(unsigned a, unsigned cnt) {
    asm volatile("mbarrier.init.shared.b64 [%0], %1;" :: "r"(a), "r"(cnt) : "memory");
}
__device__ __forceinline__ void mbar_expect(unsigned a, unsigned bytes) {
    asm volatile("mbarrier.arrive.expect_tx.shared.b64 _, [%0], %1;"
                 :: "r"(a), "r"(bytes) : "memory");
}
__device__ __forceinline__ void bulk_g2s(unsigned dst, const void* src,
                                         unsigned bytes, unsigned mbar) {
    asm volatile(
        "cp.async.bulk.shared::cluster.global.mbarrier::complete_tx::bytes "
        "[%0], [%1], %2, [%3];"
        :: "r"(dst), "l"(src), "r"(bytes), "r"(mbar) : "memory");
}
__device__ __forceinline__ void mbar_wait(unsigned a, unsigned parity) {
    asm volatile(
        "{\n\t.reg .pred P;\n\t"
        "W%=:\n\t"
        "mbarrier.try_wait.parity.shared.b64 P, [%0], %1, 0x989680;\n\t"
        "@P bra D%=;\n\t"
        "bra W%=;\n\t"
        "D%=:\n\t}"
        :: "r"(a), "r"(parity) : "memory");
}

#define LDSM4(r, addr) \
    asm volatile("ldmatrix.sync.aligned.m8n8.x4.shared.b16 {%0,%1,%2,%3}, [%4];" \
        : "=r"((r)[0]), "=r"((r)[1]), "=r"((r)[2]), "=r"((r)[3]) : "r"(addr))
#define LDSM2(r, addr) \
    asm volatile("ldmatrix.sync.aligned.m8n8.x2.shared.b16 {%0,%1}, [%2];" \
        : "=r"((r)[0]), "=r"((r)[1]) : "r"(addr))
#define MMAH16816(c, a, b0v, b1v) \
    asm volatile("mma.sync.aligned.m16n8k16.row.col.f32.f16.f16.f32 " \
        "{%0,%1,%2,%3}, {%4,%5,%6,%7}, {%8,%9}, {%0,%1,%2,%3};" \
        : "+f"((c)[0]), "+f"((c)[1]), "+f"((c)[2]), "+f"((c)[3]) \
        : "r"((a)[0]), "r"((a)[1]), "r"((a)[2]), "r"((a)[3]), "r"(b0v), "r"(b1v))

// n-half k-steps: A x4 + B x2 -> 1 MMA into the given accumulator
#define KSTEPN(cacc, aHI, bADDR) do {                     \
    unsigned ah[4], bh[2];                                \
    LDSM4(ah, aHI); LDSM2(bh, bADDR);                     \
    MMAH16816(cacc, ah, bh[0], bh[1]);                    \
} while (0)
// feats k-step: A x4 + B x4 -> 2 MMA into feats carry accumulators
#define KSTEPF(aHI, bADDR) do {                           \
    unsigned ah[4], bh[4];                                \
    LDSM4(ah, aHI); LDSM4(bh, bADDR);                     \
    MMAH16816(fcn0, ah, bh[0], bh[1]);                    \
    MMAH16816(fcn1, ah, bh[2], bh[3]);                    \
} while (0)

__device__ __forceinline__ float sigf(float x) {
    return __fdividef(1.0f, 1.0f + __expf(-x));
}
__device__ __forceinline__ float tanhfast(float x) {
    return __fdividef(2.0f, 1.0f + __expf(-2.0f * x)) - 1.0f;
}
__device__ __forceinline__ unsigned short f16r(float v) {
    __half h = __float2half_rn(v);
    unsigned short r; memcpy(&r, &h, 2); return r;
}

// ============================================================ reset
__global__ void reset_kernel() {
    int t = blockIdx.x * blockDim.x + threadIdx.x;
    if (t < 64) g_ctrs[t] = 0u;
    if (t < (int)(sizeof(g_hx) / 4)) ((unsigned*)g_hx)[t] = 0u;
}

// ============================================================ preprocessing
__global__ void prep_kernel(const float* __restrict__ x) {
    int s = blockIdx.x;
    int b = threadIdx.x;                 // 64 threads
    int grp = b >> 4, bl = b & 15;
    unsigned short* fh = g_fx + ((size_t)s * NGRP + grp) * 16 * XFST + bl * XFST;
    #pragma unroll 4
    for (int c = 0; c < XFST; c++) fh[c] = 0;

    const float* xp = x + ((size_t)b * S + s) * XW;
    float cx = xp[0], cy = xp[1];
    #pragma unroll
    for (int hnd = 0; hnd < 2; hnd++) {
        int pbase = (hnd == 0) ? 91 : 112;
        float mnx = 1e30f, mxx = -1e30f, mny = 1e30f, mxy = -1e30f;
        #pragma unroll
        for (int p = 0; p < 21; p++) {
            float px = xp[(pbase + p) * 2];
            float py = xp[(pbase + p) * 2 + 1];
            mnx = fminf(mnx, px); mxx = fmaxf(mxx, px);
            mny = fminf(mny, py); mxy = fmaxf(mxy, py);
        }
        float whx = mxx - mnx, why = mxy - mny;
        bool ok = (whx != 0.0f) && (why != 0.0f);
        float sx = ok ? whx : 1.0f;
        float sy = ok ? why : 1.0f;
        #pragma unroll
        for (int p = 0; p < 21; p++) {
            float px = (xp[(pbase + p) * 2] - cx) / sx;
            float py = (xp[(pbase + p) * 2 + 1] - cy) / sy;
            int i0 = hnd * 42 + p * 2;
            fh[i0]     = f16r(px);
            fh[i0 + 1] = f16r(py);
        }
    }
    fh[84] = f16r(1.0f);   // bias row
}

// ============================================================ recurrence (fp16 HMMA, chunked h TMA)
__global__ void __launch_bounds__(NTH, 1)
lstm_kernel(const float* __restrict__ W_ih, const float* __restrict__ W_hh,
            const float* __restrict__ b_ih, const float* __restrict__ b_hh) {
    extern __shared__ char smc[];
    const int t = threadIdx.x;
    const int blk = blockIdx.x;
    const int grp = blk >> 5;
    const int cg = blk & 31;
    const int lane = t & 31;
    const int wid = t >> 5;
    const int wg = wid >> 2;             // 0/1: K-split group
    const unsigned sbase = smem_u32(smc);

    // ---- one-time W staging: fp16, [64 rows][648 cols] (cols < 608 live) ----
    for (int idx = t; idx < 64 * 608; idx += NTH) {
        int r = idx & 63, k = idx >> 6;
        int grow = (r >> 4) * H + cg * UPC + (r & 15);
        float w;
        if (k < 512)        w = W_hh[(size_t)grow * H + k];
        else if (k < 596)   w = W_ih[(size_t)grow * IN + (k - 512)];
        else if (k == 596)  w = b_ih[grow] + b_hh[grow];
        else                w = 0.0f;
        ((__half*)(smc + OFF_WHI))[r * WST + k] = __float2half_rn(w);
    }
    if (t == 0) {
        mbar_init(sbase + OFF_MB + 0, 1);    // h chunk0 (batches 0-7)
        mbar_init(sbase + OFF_MB + 8, 1);    // h chunk1 (batches 8-15)
        mbar_init(sbase + OFF_MB + 16, 1);   // feats buf0
        mbar_init(sbase + OFF_MB + 24, 1);   // feats buf1
    }
    __syncthreads();

    const unsigned mbh0 = sbase + OFF_MB;
    const unsigned mbh1 = sbase + OFF_MB + 8;
    const unsigned mbf  = sbase + OFF_MB + 16;

    // ldmatrix per-lane addresses
    const unsigned aA = (unsigned)(((wid & 3) * 16 + (lane & 15)) * WST + (lane >> 4) * 8) * 2;
    const unsigned aAhi = sbase + OFF_WHI + aA;
    // B x2 (n-half): lanes 0-7 -> (n, k+0), lanes 8-15 -> (n, k+8); lanes 16-31 unused
    // B x4 (feats): lanes 0-7: n0-7,k+0 | 8-15: n0-7,k+8 | 16-23: n8-15,k+0 | 24-31: n8-15,k+8
    const unsigned nrow = (lane & 7) + ((lane >> 4) & 1) * 8;
    const unsigned kofs = ((lane >> 3) & 1) * 8;
    const unsigned aBh0 = sbase + OFF_XH + (unsigned)((lane & 7) * XHST + kofs) * 2;  // rows 0-7
    const unsigned aBh1 = aBh0 + (unsigned)(8 * XHST) * 2;                            // rows 8-15
    const unsigned aBf = (unsigned)(nrow * XFST + kofs) * 2;

    // gate mapping
    const int ul = t & 15, gb = t >> 4;
    const int u_glob = cg * UPC + ul;
    float creg = 0.0f;

    float* gsh  = (float*)(smc + OFF_GSH);        // plane 0
    float* gsh1 = gsh + GSHPL;                    // plane 1
    float* hout = (float*)(smc + OFF_HOUT);
    unsigned* my_ctr = &g_ctrs[grp * 16];
    const unsigned short* hsrc_base = g_hx + (size_t)grp * 16 * XHST;
    const unsigned short* fsrc_base = g_fx + (size_t)grp * 16 * XFST;

    float* gshp = gsh + wg * GSHPL;               // this warp-group's output plane

    // ---- preloop: issue h(0) chunks + feats(0); feats MMA for s=0 ----
    if (t == 0) {
        asm volatile("fence.proxy.async;" ::: "memory");
        mbar_expect(mbh0, XHCHUNK);
        bulk_g2s(sbase + OFF_XH, hsrc_base, XHCHUNK, mbh0);
        mbar_expect(mbh1, XHCHUNK);
        bulk_g2s(sbase + OFF_XH + XHCHUNK,
                 hsrc_base + 8 * XHST, XHCHUNK, mbh1);
        mbar_expect(mbf, XFBUF);
        bulk_g2s(sbase + OFF_XF, fsrc_base, XFBUF, mbf);
    }

    // feats carry accumulators (feats + bias contribution for step s)
    float fcn0[4] = {0, 0, 0, 0};
    float fcn1[4] = {0, 0, 0, 0};
    mbar_wait(mbf, 0);
    {
        const unsigned fba = sbase + OFF_XF + aBf;
        #pragma unroll
        for (int j = 0; j < 3; j++) {
            int jg = wg * 3 + j;
            KSTEPF(aAhi + 1024 + jg * 32, fba + jg * 32);
        }
    }

    for (int s = 0; s < S; s++) {
        const int nxt = (s & 1) ^ 1;
        const unsigned par = (unsigned)(s & 1);

        // ---- t0: prefetch feats(s+1) ----
        if (t == 0 && s + 1 < S) {
            int nb = (s + 1) & 1;
            mbar_expect(mbf + nb * 8, XFBUF);
            bulk_g2s(sbase + OFF_XF + (unsigned)nb * XFBUF,
                     fsrc_base + (size_t)(s + 1) * NGRP * 16 * XFST,
                     XFBUF, mbf + nb * 8);
        }

        {
            float cn0[4] = {fcn0[0], fcn0[1], fcn0[2], fcn0[3]};
            float cn1[4] = {fcn1[0], fcn1[1], fcn1[2], fcn1[3]};

            // ---- h k-steps on chunk 0 (batches 0-7) as soon as it lands ----
            mbar_wait(mbh0, par);
            #pragma unroll 4
            for (int j = 0; j < 16; j++) {
                int jg = wg * 16 + j;
                KSTEPN(cn0, aAhi + jg * 32, aBh0 + jg * 32);
            }
            // ---- chunk 1 (batches 8-15); arrives during the cn0 span ----
            mbar_wait(mbh1, par);
            #pragma unroll 4
            for (int j = 0; j < 16; j++) {
                int jg = wg * 16 + j;
                KSTEPN(cn1, aAhi + jg * 32, aBh1 + jg * 32);
            }

            // ---- D writeback to own gsh plane ----
            int r0 = (wid & 3) * 16 + (lane >> 2);
            int c0 = (lane & 3) * 2;
            gshp[r0 * 17 + c0]           = cn0[0];
            gshp[r0 * 17 + c0 + 1]       = cn0[1];
            gshp[(r0 + 8) * 17 + c0]     = cn0[2];
            gshp[(r0 + 8) * 17 + c0 + 1] = cn0[3];
            gshp[r0 * 17 + 8 + c0]           = cn1[0];
            gshp[r0 * 17 + 8 + c0 + 1]       = cn1[1];
            gshp[(r0 + 8) * 17 + 8 + c0]     = cn1[2];
            gshp[(r0 + 8) * 17 + 8 + c0 + 1] = cn1[3];
        }
        __syncthreads();

        // ---- gates: thread = (unit ul, batch gb); sum the two K-split planes ----
        {
            float gi = gsh[(0 * 16 + ul) * 17 + gb] + gsh1[(0 * 16 + ul) * 17 + gb];
            float gf = gsh[(1 * 16 + ul) * 17 + gb] + gsh1[(1 * 16 + ul) * 17 + gb];
            float gg = gsh[(2 * 16 + ul) * 17 + gb] + gsh1[(2 * 16 + ul) * 17 + gb];
            float go = gsh[(3 * 16 + ul) * 17 + gb] + gsh1[(3 * 16 + ul) * 17 + gb];
            float i_ = sigf(gi), f_ = sigf(gf);
            float g_ = tanhfast(gg), o_ = sigf(go);
            creg = f_ * creg + i_ * g_;
            float hn = o_ * tanhfast(creg);
            size_t hbase = (size_t)(nxt * NGRP + grp) * 16 * XHST;
            g_hx[hbase + gb * XHST + u_glob] = f16r(hn);
            hout[ul * 17 + gb] = hn;
        }
        __syncthreads();
        {
            int u2 = t >> 4, b2 = t & 15;
            g_lstm[((size_t)s * H + cg * UPC + u2) * B + grp * BPG + b2] =
                hout[u2 * 17 + b2];
        }

        // ---- tail: arrive; feats MMA for s+1 under barrier drain; poll; issue h(s+1) ----
        if (s != S - 1) {
            if (t == 0) {
                asm volatile("red.add.release.gpu.u32 [%0], %1;"
                             :: "l"(my_ctr), "r"(1u) : "memory");
            }
            {
                const int fb2 = (s + 1) & 1;
                const unsigned fpar2 = (unsigned)(((s + 1) >> 1) & 1);
                mbar_wait(mbf + fb2 * 8, fpar2);
                fcn0[0] = fcn0[1] = fcn0[2] = fcn0[3] = 0.0f;
                fcn1[0] = fcn1[1] = fcn1[2] = fcn1[3] = 0.0f;
                const unsigned fba = sbase + OFF_XF + (unsigned)fb2 * XFBUF + aBf;
                #pragma unroll
                for (int j = 0; j < 3; j++) {
                    int jg = wg * 3 + j;
                    KSTEPF(aAhi + 1024 + jg * 32, fba + jg * 32);
                }
            }
            if (t == 0) {
                unsigned target = (unsigned)(s + 1) * GCTA;
                unsigned v;
                do {
                    asm volatile("ld.acquire.gpu.u32 %0, [%1];"
                                 : "=r"(v) : "l"(my_ctr) : "memory");
                } while (v < target);
                // h(s+1) now globally visible -> issue chunked TMA immediately
                asm volatile("fence.proxy.async;" ::: "memory");
                const unsigned short* hsrc =
                    hsrc_base + (size_t)(nxt * NGRP) * 16 * XHST;
                mbar_expect(mbh0, XHCHUNK);
                bulk_g2s(sbase + OFF_XH, hsrc, XHCHUNK, mbh0);
                mbar_expect(mbh1, XHCHUNK);
                bulk_g2s(sbase + OFF_XH + XHCHUNK, hsrc + 8 * XHST,
                         XHCHUNK, mbh1);
            }
            __syncthreads();
        }
    }
}

// ============================================================ attention
__global__ void __launch_bounds__(256)
scores_kernel(const float* __restrict__ attn_w) {
    __shared__ float aw[H];
    __shared__ float part[4 * 64];
    int t = threadIdx.x, s = blockIdx.x;
    int st = t >> 6, b = t & 63;
    for (int i = t; i < H; i += 256) aw[i] = attn_w[i];
    __syncthreads();
    const float* Ls = g_lstm + (size_t)s * H * B;
    float acc = 0.0f;
    #pragma unroll 8
    for (int h = st * 128; h < st * 128 + 128; h++)
        acc = fmaf(aw[h], Ls[h * B + b], acc);
    part[st * 64 + b] = acc;
    __syncthreads();
    if (st == 0)
        g_sc[s * B + b] = part[b] + part[64 + b] + part[128 + b] + part[192 + b];
}

__global__ void __launch_bounds__(256)
softmax_kernel(float* __restrict__ out) {
    __shared__ float s_red[8];
    int b = blockIdx.x, t = threadIdx.x;
    int lane = t & 31, warp = t >> 5;
    float v[2];
    v[0] = g_sc[t * B + b];
    v[1] = g_sc[(t + 256) * B + b];
    float m = fmaxf(v[0], v[1]);
    #pragma unroll
    for (int o = 16; o; o >>= 1) m = fmaxf(m, __shfl_xor_sync(~0u, m, o));
    if (lane == 0) s_red[warp] = m;
    __syncthreads();
    m = s_red[0];
    #pragma unroll
    for (int i = 1; i < 8; i++) m = fmaxf(m, s_red[i]);
    __syncthreads();
    float e0 = expf(v[0] - m), e1 = expf(v[1] - m);
    float sum = e0 + e1;
    #pragma unroll
    for (int o = 16; o; o >>= 1) sum += __shfl_xor_sync(~0u, sum, o);
    if (lane == 0) s_red[warp] = sum;
    __syncthreads();
    float tot = 0.0f;
    #pragma unroll
    for (int i = 0; i < 8; i++) tot += s_red[i];
    float inv = 1.0f / tot;
    float w0 = e0 * inv, w1 = e1 * inv;
    g_sc[t * B + b] = w0;
    g_sc[(t + 256) * B + b] = w1;
    out[NC * B + b * S + t] = w0;
    out[NC * B + b * S + t + 256] = w1;
}

__global__ void __launch_bounds__(256)
ctx_kernel() {
    __shared__ float part[4 * 64];
    int t = threadIdx.x, h = blockIdx.x;
    int st = t >> 6, b = t & 63;
    float acc = 0.0f;
    const float* Lb = g_lstm + (size_t)h * B + b;
    #pragma unroll 8
    for (int s = st * 128; s < st * 128 + 128; s++)
        acc = fmaf(g_sc[s * B + b], Lb[(size_t)s * H * B], acc);
    part[st * 64 + b] = acc;
    __syncthreads();
    if (st == 0)
        g_ctx[h * B + b] = part[b] + part[64 + b] + part[128 + b] + part[192 + b];
}

__global__ void __launch_bounds__(64)
fc_kernel(const float* __restrict__ fc_w, const float* __restrict__ fc_b,
          float* __restrict__ out) {
    __shared__ float wrow[H];
    int c = blockIdx.x, b = threadIdx.x;
    for (int i = b; i < H; i += 64) wrow[i] = fc_w[(size_t)c * H + i];
    __syncthreads();
    float acc = fc_b[c];
    #pragma unroll 8
    for (int h = 0; h < H; h++)
        acc = fmaf(wrow[h], g_ctx[h * B + b], acc);
    out[b * NC + c] = acc;
}

// ============================================================ launch
extern "C" void kernel_launch(void* const* d_in, const int* in_sizes, int n_in,
                              void* d_out, int out_size) {
    const float* x      = (const float*)d_in[0];
    const float* W_ih   = (const float*)d_in[1];
    const float* W_hh   = (const float*)d_in[2];
    const float* b_ih   = (const float*)d_in[3];
    const float* b_hh   = (const float*)d_in[4];
    const float* attn_w = (const float*)d_in[5];
    const float* fc_w   = (const float*)d_in[6];
    const float* fc_b   = (const float*)d_in[7];
    float* out = (float*)d_out;

    cudaFuncSetAttribute(lstm_kernel,
                         cudaFuncAttributeMaxDynamicSharedMemorySize, SMEM_BYTES);

    reset_kernel<<<260, 256>>>();
    prep_kernel<<<S, 64>>>(x);
    lstm_kernel<<<NCTA, NTH, SMEM_BYTES>>>(W_ih, W_hh, b_ih, b_hh);
    scores_kernel<<<S, 256>>>(attn_w);
    softmax_kernel<<<B, 256>>>(out);
    ctx_kernel<<<H, 256>>>();
    fc_kernel<<<NC, 64>>>(fc_w, fc_b, out);
}

// round 17
// speedup vs baseline: 1.0824x; 1.0824x over previous
#include <cuda_runtime.h>
#include <cuda_fp16.h>
#include <math.h>

#define B 64
#define S 512
#define H 512
#define IN 84
#define NC 100
#define XW 266

#define NGRP 4
#define GCTA 32
#define BPG 16
#define UPC 16
#define NCTA 128
#define NTH 256

// padded strides (halves): row stride ≡ odd*16 B mod 128 -> conflict-free ldmatrix
#define WST 648
#define XHST 520
#define XFST 136

// ---- static device scratch ----
__device__ unsigned short g_hx[2 * NGRP * 16 * XHST];            // [par][grp][16b][520] fp16
__device__ unsigned short g_fx[(size_t)S * NGRP * 16 * XFST];    // [s][grp][16b][136] fp16
__device__ float g_lstm[(size_t)S * H * B];                      // [S][H][B]
__device__ float g_sc[S * B];
__device__ float g_ctx[H * B];
__device__ unsigned g_ctrs[64];

// ---- SMEM layout (bytes) ----
#define OFF_WHI   0                     // 64 x 648 fp16 = 82944
#define OFF_XH    82944                 // 16 x 520 fp16 = 16640
#define OFF_XF    99584                 // 2 bufs x 16 x 136 fp16 = 8704
#define OFF_GSH   108288                // 2 planes x 64 x 17 f32 = 8704
#define OFF_HOUT  116992                // 16 x 17 f32
#define OFF_MB    118080                // 3 mbars
#define SMEM_BYTES 118112
#define XFBUF 4352                      // bytes per feats buffer
#define XHBYTES 16640                   // h plane bytes
#define GSHPL 1088                      // floats per gsh plane (64*17)

// ---- helpers ----
__device__ __forceinline__ unsigned smem_u32(const void* p) {
    return (unsigned)__cvta_generic_to_shared(p);
}
__device__ __forceinline__ void mbar_init(unsigned a, unsigned cnt) {
    asm volatile("mbarrier.init.shared.b64 [%0], %1;" :: "r"(a), "r"(cnt) : "memory");
}
__device__ __forceinline__ void mbar_expect(unsigned a, unsigned bytes) {
    asm volatile("mbarrier.arrive.expect_tx.shared.b64 _, [%0], %1;"
                 :: "r"(a), "r"(bytes) : "memory");
}
__device__ __forceinline__ void bulk_g2s(unsigned dst, const void* src,
                                         unsigned bytes, unsigned mbar) {
    asm volatile(
        "cp.async.bulk.shared::cluster.global.mbarrier::complete_tx::bytes "
        "[%0], [%1], %2, [%3];"
        :: "r"(dst), "l"(src), "r"(bytes), "r"(mbar) : "memory");
}
__device__ __forceinline__ void mbar_wait(unsigned a, unsigned parity) {
    asm volatile(
        "{\n\t.reg .pred P;\n\t"
        "W%=:\n\t"
        "mbarrier.try_wait.parity.shared.b64 P, [%0], %1, 0x989680;\n\t"
        "@P bra D%=;\n\t"
        "bra W%=;\n\t"
        "D%=:\n\t}"
        :: "r"(a), "r"(parity) : "memory");
}

#define LDSM4(r, addr) \
    asm volatile("ldmatrix.sync.aligned.m8n8.x4.shared.b16 {%0,%1,%2,%3}, [%4];" \
        : "=r"((r)[0]), "=r"((r)[1]), "=r"((r)[2]), "=r"((r)[3]) : "r"(addr))
#define MMAH16816(c, a, b0v, b1v) \
    asm volatile("mma.sync.aligned.m16n8k16.row.col.f32.f16.f16.f32 " \
        "{%0,%1,%2,%3}, {%4,%5,%6,%7}, {%8,%9}, {%0,%1,%2,%3};" \
        : "+f"((c)[0]), "+f"((c)[1]), "+f"((c)[2]), "+f"((c)[3]) \
        : "r"((a)[0]), "r"((a)[1]), "r"((a)[2]), "r"((a)[3]), "r"(b0v), "r"(b1v))

// one k-step, single-pass W: A x4 fragment, B x4 fragment; 2 MMA into (cn0, cn1)
#define KSTEP1(aHI, bADDR) do {                           \
    unsigned ah[4], bh[4];                                \
    LDSM4(ah, aHI); LDSM4(bh, bADDR);                     \
    MMAH16816(cn0, ah, bh[0], bh[1]);                     \
    MMAH16816(cn1, ah, bh[2], bh[3]);                     \
} while (0)
// feats variant accumulating into carry registers (fcn0, fcn1)
#define KSTEPF(aHI, bADDR) do {                           \
    unsigned ah[4], bh[4];                                \
    LDSM4(ah, aHI); LDSM4(bh, bADDR);                     \
    MMAH16816(fcn0, ah, bh[0], bh[1]);                    \
    MMAH16816(fcn1, ah, bh[2], bh[3]);                    \
} while (0)

__device__ __forceinline__ float sigf(float x) {
    return __fdividef(1.0f, 1.0f + __expf(-x));
}
__device__ __forceinline__ float tanhfast(float x) {
    return __fdividef(2.0f, 1.0f + __expf(-2.0f * x)) - 1.0f;
}
__device__ __forceinline__ unsigned short f16r(float v) {
    __half h = __float2half_rn(v);
    unsigned short r; memcpy(&r, &h, 2); return r;
}

// ============================================================ reset
__global__ void reset_kernel() {
    int t = blockIdx.x * blockDim.x + threadIdx.x;
    if (t < 64) g_ctrs[t] = 0u;
    if (t < (int)(sizeof(g_hx) / 4)) ((unsigned*)g_hx)[t] = 0u;
}

// ============================================================ preprocessing
__global__ void prep_kernel(const float* __restrict__ x) {
    int s = blockIdx.x;
    int b = threadIdx.x;                 // 64 threads
    int grp = b >> 4, bl = b & 15;
    unsigned short* fh = g_fx + ((size_t)s * NGRP + grp) * 16 * XFST + bl * XFST;
    #pragma unroll 4
    for (int c = 0; c < XFST; c++) fh[c] = 0;

    const float* xp = x + ((size_t)b * S + s) * XW;
    float cx = xp[0], cy = xp[1];
    #pragma unroll
    for (int hnd = 0; hnd < 2; hnd++) {
        int pbase = (hnd == 0) ? 91 : 112;
        float mnx = 1e30f, mxx = -1e30f, mny = 1e30f, mxy = -1e30f;
        #pragma unroll
        for (int p = 0; p < 21; p++) {
            float px = xp[(pbase + p) * 2];
            float py = xp[(pbase + p) * 2 + 1];
            mnx = fminf(mnx, px); mxx = fmaxf(mxx, px);
            mny = fminf(mny, py); mxy = fmaxf(mxy, py);
        }
        float whx = mxx - mnx, why = mxy - mny;
        bool ok = (whx != 0.0f) && (why != 0.0f);
        float sx = ok ? whx : 1.0f;
        float sy = ok ? why : 1.0f;
        #pragma unroll
        for (int p = 0; p < 21; p++) {
            float px = (xp[(pbase + p) * 2] - cx) / sx;
            float py = (xp[(pbase + p) * 2 + 1] - cy) / sy;
            int i0 = hnd * 42 + p * 2;
            fh[i0]     = f16r(px);
            fh[i0 + 1] = f16r(py);
        }
    }
    fh[84] = f16r(1.0f);   // bias row
}

// ============================================================ recurrence (fp16 HMMA 1-pass, pipelined feats)
__global__ void __launch_bounds__(NTH, 1)
lstm_kernel(const float* __restrict__ W_ih, const float* __restrict__ W_hh,
            const float* __restrict__ b_ih, const float* __restrict__ b_hh) {
    extern __shared__ char smc[];
    const int t = threadIdx.x;
    const int blk = blockIdx.x;
    const int grp = blk >> 5;
    const int cg = blk & 31;
    const int lane = t & 31;
    const int wid = t >> 5;
    const int wg = wid >> 2;             // 0/1: K-split group
    const unsigned sbase = smem_u32(smc);

    // ---- one-time W staging: fp16, [64 rows][648 cols] (cols < 608 live) ----
    for (int idx = t; idx < 64 * 608; idx += NTH) {
        int r = idx & 63, k = idx >> 6;
        int grow = (r >> 4) * H + cg * UPC + (r & 15);
        float w;
        if (k < 512)        w = W_hh[(size_t)grow * H + k];
        else if (k < 596)   w = W_ih[(size_t)grow * IN + (k - 512)];
        else if (k == 596)  w = b_ih[grow] + b_hh[grow];
        else                w = 0.0f;
        ((__half*)(smc + OFF_WHI))[r * WST + k] = __float2half_rn(w);
    }
    if (t == 0) {
        mbar_init(sbase + OFF_MB + 0, 1);    // h
        mbar_init(sbase + OFF_MB + 8, 1);    // feats buf0
        mbar_init(sbase + OFF_MB + 16, 1);   // feats buf1
    }
    __syncthreads();

    const unsigned mbh = sbase + OFF_MB;
    const unsigned mbf = sbase + OFF_MB + 8;

    // ldmatrix per-lane addresses
    const unsigned aA = (unsigned)(((wid & 3) * 16 + (lane & 15)) * WST + (lane >> 4) * 8) * 2;
    const unsigned aAhi = sbase + OFF_WHI + aA;
    // B non-trans from [n][k] storage:
    //  lanes 0-7: n0-7,k+0 | 8-15: n0-7,k+8 | 16-23: n8-15,k+0 | 24-31: n8-15,k+8
    const unsigned nrow = (lane & 7) + ((lane >> 4) & 1) * 8;
    const unsigned kofs = ((lane >> 3) & 1) * 8;
    const unsigned aBh = sbase + OFF_XH + (unsigned)(nrow * XHST + kofs) * 2;
    const unsigned aBf = (unsigned)(nrow * XFST + kofs) * 2;

    // gate mapping
    const int ul = t & 15, gb = t >> 4;
    const int u_glob = cg * UPC + ul;
    float creg = 0.0f;

    float* gsh  = (float*)(smc + OFF_GSH);        // plane 0
    float* gsh1 = gsh + GSHPL;                    // plane 1
    float* hout = (float*)(smc + OFF_HOUT);
    unsigned* my_ctr = &g_ctrs[grp * 16];
    const unsigned short* hsrc_base = g_hx + (size_t)grp * 16 * XHST;
    const unsigned short* fsrc_base = g_fx + (size_t)grp * 16 * XFST;

    float* gshp = gsh + wg * GSHPL;               // this warp-group's output plane

    // ---- preloop: issue h(0) + feats(0); feats MMA for s=0 ----
    if (t == 0) {
        asm volatile("fence.proxy.async;" ::: "memory");
        mbar_expect(mbh, XHBYTES);
        bulk_g2s(sbase + OFF_XH, hsrc_base, XHBYTES, mbh);
        mbar_expect(mbf, XFBUF);
        bulk_g2s(sbase + OFF_XF, fsrc_base, XFBUF, mbf);
    }

    // feats carry accumulators: hold the feats+bias contribution for step s
    float fcn0[4] = {0, 0, 0, 0};
    float fcn1[4] = {0, 0, 0, 0};
    mbar_wait(mbf, 0);
    {
        const unsigned fba = sbase + OFF_XF + aBf;
        #pragma unroll
        for (int j = 0; j < 3; j++) {
            int jg = wg * 3 + j;
            KSTEPF(aAhi + 1024 + jg * 32, fba + jg * 32);
        }
    }

    for (int s = 0; s < S; s++) {
        const int nxt = (s & 1) ^ 1;
        const unsigned par = (unsigned)(s & 1);

        // ---- t0: prefetch feats(s+1) (h(s) already issued in previous tail) ----
        if (t == 0 && s + 1 < S) {
            int nb = (s + 1) & 1;
            mbar_expect(mbf + nb * 8, XFBUF);
            bulk_g2s(sbase + OFF_XF + (unsigned)nb * XFBUF,
                     fsrc_base + (size_t)(s + 1) * NGRP * 16 * XFST,
                     XFBUF, mbf + nb * 8);
        }

        {
            float cn0[4] = {fcn0[0], fcn0[1], fcn0[2], fcn0[3]};
            float cn1[4] = {fcn1[0], fcn1[1], fcn1[2], fcn1[3]};

            // ---- h k-steps (16 per K-split group; W cols 0..511) ----
            mbar_wait(mbh, par);
            #pragma unroll 4
            for (int j = 0; j < 16; j++) {
                int jg = wg * 16 + j;
                KSTEP1(aAhi + jg * 32, aBh + jg * 32);
            }

            // ---- D writeback to own gsh plane ----
            int r0 = (wid & 3) * 16 + (lane >> 2);
            int c0 = (lane & 3) * 2;
            gshp[r0 * 17 + c0]           = cn0[0];
            gshp[r0 * 17 + c0 + 1]       = cn0[1];
            gshp[(r0 + 8) * 17 + c0]     = cn0[2];
            gshp[(r0 + 8) * 17 + c0 + 1] = cn0[3];
            gshp[r0 * 17 + 8 + c0]           = cn1[0];
            gshp[r0 * 17 + 8 + c0 + 1]       = cn1[1];
            gshp[(r0 + 8) * 17 + 8 + c0]     = cn1[2];
            gshp[(r0 + 8) * 17 + 8 + c0 + 1] = cn1[3];
        }
        __syncthreads();

        // ---- gates: thread = (unit ul, batch gb); sum the two K-split planes ----
        {
            float gi = gsh[(0 * 16 + ul) * 17 + gb] + gsh1[(0 * 16 + ul) * 17 + gb];
            float gf = gsh[(1 * 16 + ul) * 17 + gb] + gsh1[(1 * 16 + ul) * 17 + gb];
            float gg = gsh[(2 * 16 + ul) * 17 + gb] + gsh1[(2 * 16 + ul) * 17 + gb];
            float go = gsh[(3 * 16 + ul) * 17 + gb] + gsh1[(3 * 16 + ul) * 17 + gb];
            float i_ = sigf(gi), f_ = sigf(gf);
            float g_ = tanhfast(gg), o_ = sigf(go);
            creg = f_ * creg + i_ * g_;
            float hn = o_ * tanhfast(creg);
            size_t hbase = (size_t)(nxt * NGRP + grp) * 16 * XHST;
            g_hx[hbase + gb * XHST + u_glob] = f16r(hn);
            hout[ul * 17 + gb] = hn;
        }
        __syncthreads();
        {
            int u2 = t >> 4, b2 = t & 15;
            g_lstm[((size_t)s * H + cg * UPC + u2) * B + grp * BPG + b2] =
                hout[u2 * 17 + b2];
        }

        // ---- tail: arrive; feats MMA for s+1 under barrier drain; poll; issue h(s+1) ----
        if (s != S - 1) {
            if (t == 0) {
                asm volatile("red.add.release.gpu.u32 [%0], %1;"
                             :: "l"(my_ctr), "r"(1u) : "memory");
            }
            // feats MMA for s+1 (prefetched; independent of the barrier)
            {
                const int fb2 = (s + 1) & 1;
                const unsigned fpar2 = (unsigned)(((s + 1) >> 1) & 1);
                mbar_wait(mbf + fb2 * 8, fpar2);
                fcn0[0] = fcn0[1] = fcn0[2] = fcn0[3] = 0.0f;
                fcn1[0] = fcn1[1] = fcn1[2] = fcn1[3] = 0.0f;
                const unsigned fba = sbase + OFF_XF + (unsigned)fb2 * XFBUF + aBf;
                #pragma unroll
                for (int j = 0; j < 3; j++) {
                    int jg = wg * 3 + j;
                    KSTEPF(aAhi + 1024 + jg * 32, fba + jg * 32);
                }
            }
            if (t == 0) {
                unsigned target = (unsigned)(s + 1) * GCTA;
                unsigned v;
                do {
                    asm volatile("ld.acquire.gpu.u32 %0, [%1];"
                                 : "=r"(v) : "l"(my_ctr) : "memory");
                } while (v < target);
                // h(s+1) now globally visible -> issue its TMA immediately,
                // before the closing syncthreads
                asm volatile("fence.proxy.async;" ::: "memory");
                mbar_expect(mbh, XHBYTES);
                bulk_g2s(sbase + OFF_XH,
                         hsrc_base + (size_t)(nxt * NGRP) * 16 * XHST,
                         XHBYTES, mbh);
            }
            __syncthreads();
        }
    }
}

// ============================================================ attention
__global__ void __launch_bounds__(256)
scores_kernel(const float* __restrict__ attn_w) {
    __shared__ float aw[H];
    __shared__ float part[4 * 64];
    int t = threadIdx.x, s = blockIdx.x;
    int st = t >> 6, b = t & 63;
    for (int i = t; i < H; i += 256) aw[i] = attn_w[i];
    __syncthreads();
    const float* Ls = g_lstm + (size_t)s * H * B;
    float acc = 0.0f;
    #pragma unroll 8
    for (int h = st * 128; h < st * 128 + 128; h++)
        acc = fmaf(aw[h], Ls[h * B + b], acc);
    part[st * 64 + b] = acc;
    __syncthreads();
    if (st == 0)
        g_sc[s * B + b] = part[b] + part[64 + b] + part[128 + b] + part[192 + b];
}

__global__ void __launch_bounds__(256)
softmax_kernel(float* __restrict__ out) {
    __shared__ float s_red[8];
    int b = blockIdx.x, t = threadIdx.x;
    int lane = t & 31, warp = t >> 5;
    float v[2];
    v[0] = g_sc[t * B + b];
    v[1] = g_sc[(t + 256) * B + b];
    float m = fmaxf(v[0], v[1]);
    #pragma unroll
    for (int o = 16; o; o >>= 1) m = fmaxf(m, __shfl_xor_sync(~0u, m, o));
    if (lane == 0) s_red[warp] = m;
    __syncthreads();
    m = s_red[0];
    #pragma unroll
    for (int i = 1; i < 8; i++) m = fmaxf(m, s_red[i]);
    __syncthreads();
    float e0 = expf(v[0] - m), e1 = expf(v[1] - m);
    float sum = e0 + e1;
    #pragma unroll
    for (int o = 16; o; o >>= 1) sum += __shfl_xor_sync(~0u, sum, o);
    if (lane == 0) s_red[warp] = sum;
    __syncthreads();
    float tot = 0.0f;
    #pragma unroll
    for (int i = 0; i < 8; i++) tot += s_red[i];
    float inv = 1.0f / tot;
    float w0 = e0 * inv, w1 = e1 * inv;
    g_sc[t * B + b] = w0;
    g_sc[(t + 256) * B + b] = w1;
    out[NC * B + b * S + t] = w0;
    out[NC * B + b * S + t + 256] = w1;
}

__global__ void __launch_bounds__(256)
ctx_kernel() {
    __shared__ float part[4 * 64];
    int t = threadIdx.x, h = blockIdx.x;
    int st = t >> 6, b = t & 63;
    float acc = 0.0f;
    const float* Lb = g_lstm + (size_t)h * B + b;
    #pragma unroll 8
    for (int s = st * 128; s < st * 128 + 128; s++)
        acc = fmaf(g_sc[s * B + b], Lb[(size_t)s * H * B], acc);
    part[st * 64 + b] = acc;
    __syncthreads();
    if (st == 0)
        g_ctx[h * B + b] = part[b] + part[64 + b] + part[128 + b] + part[192 + b];
}

__global__ void __launch_bounds__(64)
fc_kernel(const float* __restrict__ fc_w, const float* __restrict__ fc_b,
          float* __restrict__ out) {
    __shared__ float wrow[H];
    int c = blockIdx.x, b = threadIdx.x;
    for (int i = b; i < H; i += 64) wrow[i] = fc_w[(size_t)c * H + i];
    __syncthreads();
    float acc = fc_b[c];
    #pragma unroll 8
    for (int h = 0; h < H; h++)
        acc = fmaf(wrow[h], g_ctx[h * B + b], acc);
    out[b * NC + c] = acc;
}

// ============================================================ launch
extern "C" void kernel_launch(void* const* d_in, const int* in_sizes, int n_in,
                              void* d_out, int out_size) {
    const float* x      = (const float*)d_in[0];
    const float* W_ih   = (const float*)d_in[1];
    const float* W_hh   = (const float*)d_in[2];
    const float* b_ih   = (const float*)d_in[3];
    const float* b_hh   = (const float*)d_in[4];
    const float* attn_w = (const float*)d_in[5];
    const float* fc_w   = (const float*)d_in[6];
    const float* fc_b   = (const float*)d_in[7];
    float* out = (float*)d_out;

    cudaFuncSetAttribute(lstm_kernel,
                         cudaFuncAttributeMaxDynamicSharedMemorySize, SMEM_BYTES);

    reset_kernel<<<260, 256>>>();
    prep_kernel<<<S, 64>>>(x);
    lstm_kernel<<<NCTA, NTH, SMEM_BYTES>>>(W_ih, W_hh, b_ih, b_hh);
    scores_kernel<<<S, 256>>>(attn_w);
    softmax_kernel<<<B, 256>>>(out);
    ctx_kernel<<<H, 256>>>();
    fc_kernel<<<NC, 64>>>(fc_w, fc_b, out);
}